// round 6
// baseline (speedup 1.0000x reference)
#include <cuda_runtime.h>

// ATCA/TCA loss, C=10, T=500, N=128, B=256.
// Chunk-per-warp layout: block = 32 neurons x 4 chunk-warps, so every LDG is
// 32 consecutive n => one 128B line. Cross-chunk merge via shared memory.

#define NEGF (-3.0e30f)

__global__ void atca_zero(float* out) { out[0] = 0.0f; }

#define INS4(x) do { float _x = (x); \
    float _a0 = fmaxf(t40, _x), _b0 = fminf(t40, _x); \
    float _a1 = fmaxf(t41, _b0), _b1 = fminf(t41, _b0); \
    float _a2 = fmaxf(t42, _b1), _b2 = fminf(t42, _b1); \
    t43 = fmaxf(t43, _b2); t42 = _a2; t41 = _a1; t40 = _a0; } while (0)

__global__ void __launch_bounds__(128)
atca4(const float* __restrict__ vmem, const int* __restrict__ labels,
      float* __restrict__ out)
{
    const int lane   = threadIdx.x & 31;
    const int c      = threadIdx.x >> 5;       // chunk = warp id (0..3)
    const int neuron = blockIdx.x * 32 + lane; // 32 consecutive neurons/block
    const int b      = neuron >> 7;
    const int n      = neuron & 127;
    const int t0     = c * 125;
    const float* __restrict__ p = vmem + ((size_t)b * 500 + t0) * 128 + n;

    // ---- left halo: last spike in [t0-10, t0), k-relative (warp-uniform c) ----
    int hl = -1000;
    if (c != 0) {
        #pragma unroll
        for (int h = 0; h < 10; ++h) {
            const float v = __ldg(p + (h - 10) * 128);
            if (v >= 0.0f) hl = h - 10;
        }
    }
    int   relB = hl + 20;       // mask threshold: s=kk-10 unmasked iff kk > relB
    int   rel  = -1000;         // local piece threshold: new piece iff kk > rel
    int   ns   = 0;             // local piece count
    int   tfk  = 100000;        // first-spike k (only relevant if < 10)
    int   tlk  = -100000;       // last-spike k (only relevant if >= 115)
    float fm = NEGF, cm = NEGF; // first-piece max, current-piece max
    float mid0 = NEGF;          // largest interior-piece max
    float msum = 0.0f;          // sum of interior-piece maxima
    float m0 = NEGF, vmax = NEGF;

    float A[16], Bb[16];

    #pragma unroll
    for (int j = 0; j < 9; ++j) {
        float*       cur = (j & 1) ? Bb : A;
        const float* prv = (j & 1) ? A : Bb;
        #pragma unroll
        for (int k = 0; k < 16; ++k) {
            const int kk = 16 * j + k;
            if (j < 7) {
                cur[k] = __ldg(p + kk * 128);       // always in-bounds
            } else {
                float v = NEGF;
                if (t0 + kk < 500) v = __ldg(p + kk * 128);
                cur[k] = v;
            }
        }
        #pragma unroll
        for (int k = 0; k < 16; ++k) {
            const int kk  = 16 * j + k;             // compile-time
            const float v = cur[k];
            const bool spk = (v >= 0.0f);
            relB = spk ? kk + 20 : relB;            // spikes incl. right overhang
            if (kk >= 10 && kk < 135) {             // compile-time window
                const float vl = (k >= 10) ? cur[k - 10] : prv[k + 6];
                if (kk > relB) m0 = fmaxf(m0, vl);
            }
            vmax = fmaxf(vmax, v);
            if (kk < 125) {                         // own range (compile-time)
                const bool newp = spk && (kk > rel);
                const bool was0 = (ns == 0);
                const bool was1 = (ns == 1);
                const bool ge2  = (ns >= 2);
                fm = (newp && was1) ? cm : fm;
                const bool pm = newp && ge2;        // retire an interior piece
                msum += pm ? cm : 0.0f;
                mid0  = pm ? fmaxf(mid0, cm) : mid0;
                const float cm1 = fmaxf(cm, v);
                cm = newp ? v : (spk ? cm1 : cm);
                ns += newp ? 1 : 0;
                if (kk < 10)   tfk = (newp && was0) ? kk : tfk;
                if (kk >= 115) tlk = spk ? kk : tlk;
                rel = spk ? kk + 10 : rel;
            }
        }
    }
    const float lm = cm;                            // last-piece max
    if (ns == 1) fm = cm;                           // single piece: fm == lm

    // ---- publish chunk state to shared memory ----
    __shared__ int   s_ns[4][32], s_tf[4][32], s_tl[4][32];
    __shared__ float s_fm[4][32], s_lm[4][32], s_mid[4][32];
    __shared__ float s_msum[4][32], s_m0[4][32], s_vm[4][32];
    s_ns[c][lane]   = ns;
    s_tf[c][lane]   = t0 + tfk;
    s_tl[c][lane]   = t0 + tlk;
    s_fm[c][lane]   = fm;
    s_lm[c][lane]   = lm;
    s_mid[c][lane]  = mid0;
    s_msum[c][lane] = msum;
    s_m0[c][lane]   = m0;
    s_vm[c][lane]   = vmax;
    __syncthreads();

    float contrib = 0.0f;
    if (c == 0) {
        const float m0g = fmaxf(fmaxf(s_m0[0][lane], s_m0[1][lane]),
                                fmaxf(s_m0[2][lane], s_m0[3][lane]));
        const float vmg = fmaxf(fmaxf(s_vm[0][lane], s_vm[1][lane]),
                                fmaxf(s_vm[2][lane], s_vm[3][lane]));

        int nc = 0; float tot = 0.0f;
        float t40 = NEGF, t41 = NEGF, t42 = NEGF, t43 = NEGF;
        bool ov = false, valid = false;
        float open = NEGF; int last_t = -100000;
        #pragma unroll
        for (int cc = 0; cc < 4; ++cc) {
            const int nsc = s_ns[cc][lane];
            if (nsc == 0) continue;                 // spike-free chunk
            const bool conn = (s_tf[cc][lane] - last_t) <= 10;
            if (conn) {
                open = fmaxf(open, s_fm[cc][lane]); // first piece extends chain
            } else {
                if (valid) { ++nc; tot += open; INS4(open); }
                open = s_fm[cc][lane]; valid = true;
            }
            if (nsc >= 2) {
                ++nc; tot += open; INS4(open);      // chain closes inside chunk
                const int mc = nsc - 2;             // interior pieces
                nc += mc; tot += s_msum[cc][lane];
                if (mc >= 1) INS4(s_mid[cc][lane]);
                if (mc >= 2) ov = true;             // top-4 may be inexact
                open = s_lm[cc][lane]; valid = true;
            }
            last_t = s_tl[cc][lane];
        }
        if (valid) { ++nc; tot += open; INS4(open); }

        const int label = labels[neuron];
        if (label > nc) {
            const bool any_un = (m0g > -1.0e29f);
            if (!any_un) {
                contrib = vmg;                      // full0: everything masked
            } else {
                float m_rest;
                if (nc > 0) {
                    m_rest = m0g;   // argmax is a spike -> mask2 == mask
                } else {
                    // cold: no spikes at all — recompute argmax window
                    int tm = 0; float vm = NEGF;
                    for (int t = 0; t < 500; ++t) {
                        const float v = __ldg(p + t * 128);
                        if (v > vm) { vm = v; tm = t; }
                    }
                    float v2 = NEGF;
                    for (int t = 0; t < 500; ++t)
                        if (t < tm - 5 || t > tm + 5)
                            v2 = fmaxf(v2, __ldg(p + t * 128));
                    const bool full2 = (tm <= 5) && (tm + 5 >= 499);
                    m_rest = full2 ? vmg : v2;
                }
                const float dE = (float)(label - nc);
                contrib = -((m0g + (dE - 1.0f) * m_rest) / dE);
            }
        } else if (label < nc) {
            if (ov && label >= 1) {
                // rare exact top-4 recompute (serial rescan; p is chunk-0 base)
                t40 = t41 = t42 = t43 = NEGF;
                int last = -1000; float cmx = NEGF; bool open2 = false;
                for (int t = 0; t < 500; ++t) {
                    const float v = __ldg(p + t * 128);
                    if (v >= 0.0f) {
                        if (t - last > 10) {
                            if (open2) INS4(cmx);
                            cmx = v; open2 = true;
                        } else {
                            cmx = fmaxf(cmx, v);
                        }
                        last = t;
                    }
                }
                if (open2) INS4(cmx);
            }
            float s = tot;                          // sum(smallest nc-label)
            if (label >= 1) s -= t40;
            if (label >= 2) s -= t41;
            if (label >= 3) s -= t42;
            if (label >= 4) s -= t43;
            contrib = s / (float)(nc - label);
        }
        out[1 + neuron] = (float)nc;                // coalesced 32-float store
    }

    // ---- loss reduction: only warp 0 has contributions ----
    if (c == 0) {
        float val = contrib;
        #pragma unroll
        for (int off = 16; off > 0; off >>= 1)
            val += __shfl_down_sync(0xffffffffu, val, off);
        if (lane == 0) atomicAdd(out, val);
    }
}

extern "C" void kernel_launch(void* const* d_in, const int* in_sizes, int n_in,
                              void* d_out, int out_size) {
    const float* vmem   = (const float*)d_in[0];
    const int*   labels = (const int*)d_in[2];
    float* out = (float*)d_out;

    atca_zero<<<1, 1>>>(out);
    // 32768 neurons / 32 per block = 1024 blocks of 128 (4 chunk-warps)
    atca4<<<1024, 128>>>(vmem, labels, out);
}

// round 7
// speedup vs baseline: 1.0039x; 1.0039x over previous
#include <cuda_runtime.h>

// ATCA/TCA loss, C=10, T=500, N=128, B=256.
// Warp-cooperative float4 staging via smem, 1-tile software pipeline:
// 4 x LDG.128 per warp per tile stay in flight during compute of the
// previous tile -> ~2KB outstanding per warp, lifting the MLP<1 ceiling
// that pinned R3-R5 at ~100us.

#define NEGF (-3.0e30f)

__global__ void atca_zero(float* out) { out[0] = 0.0f; }

#define INS4(x) do { float _x = (x); \
    float _a0 = fmaxf(t40, _x), _b0 = fminf(t40, _x); \
    float _a1 = fmaxf(t41, _b0), _b1 = fminf(t41, _b0); \
    float _a2 = fmaxf(t42, _b1), _b2 = fminf(t42, _b1); \
    t43 = fmaxf(t43, _b2); t42 = _a2; t41 = _a1; t40 = _a0; } while (0)

// load tile j (16 rows x 32 floats) into P0..P3; rows with t0+r >= 500 -> NEGF
#define LOADT(j, guarded) do { \
    const int _r0 = (j) * 16 + (lane >> 3); \
    const float4* _ap = (const float4*)(gp + (size_t)_r0 * 128) + (lane & 7); \
    if (!(guarded)) { \
        P0 = __ldg(_ap); \
        P1 = __ldg(_ap + 4 * 32); \
        P2 = __ldg(_ap + 8 * 32); \
        P3 = __ldg(_ap + 12 * 32); \
    } else { \
        const float4 _ng = make_float4(NEGF, NEGF, NEGF, NEGF); \
        P0 = (t0 + _r0      < 500) ? __ldg(_ap)           : _ng; \
        P1 = (t0 + _r0 + 4  < 500) ? __ldg(_ap + 4 * 32)  : _ng; \
        P2 = (t0 + _r0 + 8  < 500) ? __ldg(_ap + 8 * 32)  : _ng; \
        P3 = (t0 + _r0 + 12 < 500) ? __ldg(_ap + 12 * 32) : _ng; \
    } } while (0)

__global__ void __launch_bounds__(128)
atca5(const float* __restrict__ vmem, const int* __restrict__ labels,
      float* __restrict__ out)
{
    __shared__ __align__(16) float sbuf[4][2][512];   // [warp][buf][16*32]
    __shared__ int   s_ns[4][32], s_tf[4][32], s_tl[4][32];
    __shared__ float s_fm[4][32], s_lm[4][32], s_mid[4][32];
    __shared__ float s_msum[4][32], s_m0[4][32], s_vm[4][32];

    const int lane = threadIdx.x & 31;
    const int c    = threadIdx.x >> 5;          // chunk = warp id
    const int nb   = blockIdx.x * 32;           // 32-aligned neuron base
    const int b    = nb >> 7;
    const int n0   = nb & 127;
    const int neuron = nb + lane;
    const int t0   = c * 125;
    const float* __restrict__ gp = vmem + ((size_t)b * 500 + t0) * 128 + n0;
    const float* __restrict__ p  = gp + lane;   // scalar per-neuron pointer

    // ---- left halo: last spike in [t0-10, t0) ----
    int hl = -1000;
    if (c != 0) {
        #pragma unroll
        for (int h = 0; h < 10; ++h) {
            const float v = __ldg(p + (h - 10) * 128);
            if (v >= 0.0f) hl = h - 10;
        }
    }
    int   relB = hl + 20;       // s=kk-10 unmasked iff kk > relB
    int   rel  = -1000;         // new piece iff spike && kk > rel
    int   ns   = 0;
    int   tfk  = 100000;        // first-spike k (relevant if < 10)
    int   tlk  = -100000;       // last-spike k (relevant if >= 115)
    float fm = NEGF, cm = NEGF;
    float mid0 = NEGF, msum = 0.0f;
    float m0 = NEGF, vmax = NEGF;

    float4 P0, P1, P2, P3;
    LOADT(0, false);                            // prologue

    #pragma unroll
    for (int j = 0; j < 9; ++j) {
        // commit tile j to smem
        float4* bp = (float4*)sbuf[c][j & 1];
        bp[0 * 32 + lane] = P0;
        bp[1 * 32 + lane] = P1;
        bp[2 * 32 + lane] = P2;
        bp[3 * 32 + lane] = P3;
        __syncwarp();
        if (j < 8) { LOADT(j + 1, (j + 1) >= 7); }   // in flight during compute

        const float* cb = sbuf[c][j & 1];
        const float* pb = sbuf[c][(j ^ 1) & 1];
        #pragma unroll
        for (int k = 0; k < 16; ++k) {
            const int kk  = 16 * j + k;              // compile-time
            const float v = cb[k * 32 + lane];
            const bool spk = (v >= 0.0f);
            relB = spk ? kk + 20 : relB;
            if (kk >= 10 && kk < 135) {
                const float vl = (k >= 10) ? cb[(k - 10) * 32 + lane]
                                           : pb[(k + 6) * 32 + lane];
                if (kk > relB) m0 = fmaxf(m0, vl);
            }
            vmax = fmaxf(vmax, v);
            if (kk < 125) {
                const bool newp = spk && (kk > rel);
                const bool was0 = (ns == 0);
                const bool was1 = (ns == 1);
                const bool ge2  = (ns >= 2);
                fm = (newp && was1) ? cm : fm;
                const bool pm = newp && ge2;
                msum += pm ? cm : 0.0f;
                mid0  = pm ? fmaxf(mid0, cm) : mid0;
                const float cm1 = fmaxf(cm, v);
                cm = newp ? v : (spk ? cm1 : cm);
                ns += newp ? 1 : 0;
                if (kk < 10)   tfk = (newp && was0) ? kk : tfk;
                if (kk >= 115) tlk = spk ? kk : tlk;
                rel = spk ? kk + 10 : rel;
            }
        }
    }
    const float lm = cm;
    if (ns == 1) fm = cm;

    // ---- publish chunk state ----
    s_ns[c][lane]   = ns;
    s_tf[c][lane]   = t0 + tfk;
    s_tl[c][lane]   = t0 + tlk;
    s_fm[c][lane]   = fm;
    s_lm[c][lane]   = lm;
    s_mid[c][lane]  = mid0;
    s_msum[c][lane] = msum;
    s_m0[c][lane]   = m0;
    s_vm[c][lane]   = vmax;
    __syncthreads();

    if (c == 0) {
        const float m0g = fmaxf(fmaxf(s_m0[0][lane], s_m0[1][lane]),
                                fmaxf(s_m0[2][lane], s_m0[3][lane]));
        const float vmg = fmaxf(fmaxf(s_vm[0][lane], s_vm[1][lane]),
                                fmaxf(s_vm[2][lane], s_vm[3][lane]));

        int nc = 0; float tot = 0.0f;
        float t40 = NEGF, t41 = NEGF, t42 = NEGF, t43 = NEGF;
        bool ov = false, valid = false;
        float open = NEGF; int last_t = -100000;
        #pragma unroll
        for (int cc = 0; cc < 4; ++cc) {
            const int nsc = s_ns[cc][lane];
            if (nsc == 0) continue;
            const bool conn = (s_tf[cc][lane] - last_t) <= 10;
            if (conn) {
                open = fmaxf(open, s_fm[cc][lane]);
            } else {
                if (valid) { ++nc; tot += open; INS4(open); }
                open = s_fm[cc][lane]; valid = true;
            }
            if (nsc >= 2) {
                ++nc; tot += open; INS4(open);
                const int mc = nsc - 2;
                nc += mc; tot += s_msum[cc][lane];
                if (mc >= 1) INS4(s_mid[cc][lane]);
                if (mc >= 2) ov = true;
                open = s_lm[cc][lane]; valid = true;
            }
            last_t = s_tl[cc][lane];
        }
        if (valid) { ++nc; tot += open; INS4(open); }

        float contrib = 0.0f;
        const int label = labels[neuron];
        if (label > nc) {
            const bool any_un = (m0g > -1.0e29f);
            if (!any_un) {
                contrib = vmg;
            } else {
                float m_rest;
                if (nc > 0) {
                    m_rest = m0g;            // argmax is a spike -> mask2 == mask
                } else {
                    int tm = 0; float vm = NEGF;    // cold: no spikes at all
                    for (int t = 0; t < 500; ++t) {
                        const float v = __ldg(p + t * 128);
                        if (v > vm) { vm = v; tm = t; }
                    }
                    float v2 = NEGF;
                    for (int t = 0; t < 500; ++t)
                        if (t < tm - 5 || t > tm + 5)
                            v2 = fmaxf(v2, __ldg(p + t * 128));
                    const bool full2 = (tm <= 5) && (tm + 5 >= 499);
                    m_rest = full2 ? vmg : v2;
                }
                const float dE = (float)(label - nc);
                contrib = -((m0g + (dE - 1.0f) * m_rest) / dE);
            }
        } else if (label < nc) {
            if (ov && label >= 1) {
                // rare exact top-4 recompute (serial rescan)
                t40 = t41 = t42 = t43 = NEGF;
                int last = -1000; float cmx = NEGF; bool open2 = false;
                for (int t = 0; t < 500; ++t) {
                    const float v = __ldg(p + t * 128);
                    if (v >= 0.0f) {
                        if (t - last > 10) {
                            if (open2) INS4(cmx);
                            cmx = v; open2 = true;
                        } else cmx = fmaxf(cmx, v);
                        last = t;
                    }
                }
                if (open2) INS4(cmx);
            }
            float s = tot;
            if (label >= 1) s -= t40;
            if (label >= 2) s -= t41;
            if (label >= 3) s -= t42;
            if (label >= 4) s -= t43;
            contrib = s / (float)(nc - label);
        }
        out[1 + neuron] = (float)nc;

        float val = contrib;
        #pragma unroll
        for (int off = 16; off > 0; off >>= 1)
            val += __shfl_down_sync(0xffffffffu, val, off);
        if (lane == 0) atomicAdd(out, val);
    }
}

extern "C" void kernel_launch(void* const* d_in, const int* in_sizes, int n_in,
                              void* d_out, int out_size) {
    const float* vmem   = (const float*)d_in[0];
    const int*   labels = (const int*)d_in[2];
    float* out = (float*)d_out;

    atca_zero<<<1, 1>>>(out);
    // 32768 neurons / 32 per block = 1024 blocks of 128 (4 chunk-warps)
    atca5<<<1024, 128>>>(vmem, labels, out);
}

// round 8
// speedup vs baseline: 3.0195x; 3.0078x over previous
#include <cuda_runtime.h>

// ATCA/TCA loss, C=10, T=500, N=128, B=256.
// 8 chunk-warps x 32 neurons per block (chunk L=63). Per tile (16 steps x 32
// neurons): 4x LDG.128 prefetch -> 4x STS.128 -> 16x LDS.32 batched into a
// register window; all scan work and the 10-step lag run on registers.

#define NEGF (-3.0e30f)

__global__ void atca_zero(float* out) { out[0] = 0.0f; }

#define INS4(x) do { float _x = (x); \
    float _a0 = fmaxf(t40, _x), _b0 = fminf(t40, _x); \
    float _a1 = fmaxf(t41, _b0), _b1 = fminf(t41, _b0); \
    float _a2 = fmaxf(t42, _b1), _b2 = fminf(t42, _b1); \
    t43 = fmaxf(t43, _b2); t42 = _a2; t41 = _a1; t40 = _a0; } while (0)

// load tile j (16 rows x 32 neurons): rows 16j + (lane>>3) + {0,4,8,12}
#define LOADT(j, guarded) do { \
    const int _r0 = (j) * 16 + (lane >> 3); \
    const float4* _ap = (const float4*)(gp + (size_t)_r0 * 128) + (lane & 7); \
    if (!(guarded)) { \
        P0 = __ldg(_ap); \
        P1 = __ldg(_ap + 4 * 32); \
        P2 = __ldg(_ap + 8 * 32); \
        P3 = __ldg(_ap + 12 * 32); \
    } else { \
        const float4 _ng = make_float4(NEGF, NEGF, NEGF, NEGF); \
        P0 = (t0 + _r0      < 500) ? __ldg(_ap)           : _ng; \
        P1 = (t0 + _r0 + 4  < 500) ? __ldg(_ap + 4 * 32)  : _ng; \
        P2 = (t0 + _r0 + 8  < 500) ? __ldg(_ap + 8 * 32)  : _ng; \
        P3 = (t0 + _r0 + 12 < 500) ? __ldg(_ap + 12 * 32) : _ng; \
    } } while (0)

__global__ void __launch_bounds__(256)
atca8(const float* __restrict__ vmem, const int* __restrict__ labels,
      float* __restrict__ out)
{
    __shared__ __align__(16) float sbuf[8][512];      // [warp][16*32], single buf
    __shared__ int   s_ns[8][32], s_tf[8][32], s_tl[8][32];
    __shared__ float s_fm[8][32], s_lm[8][32], s_mid[8][32];
    __shared__ float s_msum[8][32], s_m0[8][32], s_vm[8][32];

    const int lane = threadIdx.x & 31;
    const int c    = threadIdx.x >> 5;          // chunk = warp id (0..7)
    const int nb   = blockIdx.x * 32;           // 32-aligned neuron base
    const int b    = nb >> 7;
    const int n0   = nb & 127;
    const int neuron = nb + lane;
    const int t0   = c * 63;                    // chunk owns [t0, t0+63)
    const float* __restrict__ gp = vmem + ((size_t)b * 500 + t0) * 128 + n0;
    const float* __restrict__ p  = gp + lane;

    // ---- left halo: last spike in [t0-10, t0) ----
    int hl = -1000;
    if (c != 0) {
        #pragma unroll
        for (int h = 0; h < 10; ++h) {
            const float v = __ldg(p + (h - 10) * 128);
            if (v >= 0.0f) hl = h - 10;
        }
    }
    int   relB = hl + 20;       // s=kk-10 unmasked iff kk > relB
    int   rel  = -1000;         // new piece iff spike && kk > rel
    int   ns   = 0;
    int   tfk  = 100000;        // first-piece k (relevant iff < 10)
    int   tlk  = -100000;       // last-spike k (relevant iff >= 53)
    float fm = NEGF, cm = NEGF;
    float mid0 = NEGF, msum = 0.0f;
    float m0 = NEGF, vmax = NEGF;

    float A[16], Bb[16];
    float4 P0, P1, P2, P3;
    LOADT(0, false);                            // prologue (rows < 457 always)

    #pragma unroll
    for (int j = 0; j < 5; ++j) {
        float*       cur = (j & 1) ? Bb : A;
        const float* prv = (j & 1) ? A : Bb;

        __syncwarp();                           // prior tile's LDS done
        float4* bp = (float4*)sbuf[c];
        bp[0 * 32 + lane] = P0;
        bp[1 * 32 + lane] = P1;
        bp[2 * 32 + lane] = P2;
        bp[3 * 32 + lane] = P3;
        if (j < 4) { LOADT(j + 1, (c == 7) && (j + 1 >= 3)); }
        __syncwarp();

        // batched LDS into register window (steps > 72 never used)
        const float* sb = sbuf[c];
        #pragma unroll
        for (int k = 0; k < 16; ++k) {
            if (16 * j + k <= 72) cur[k] = sb[k * 32 + lane];
        }
        #pragma unroll
        for (int k = 0; k < 16; ++k) {
            const int kk = 16 * j + k;          // compile-time
            if (kk > 72) continue;
            const float v = cur[k];
            const bool spk = (v >= 0.0f);
            relB = spk ? kk + 20 : relB;
            if (kk >= 10) {                     // m0 for s = kk-10 (own range)
                const float vl = (k >= 10) ? cur[k - 10] : prv[k + 6];
                if (kk > relB) m0 = fmaxf(m0, vl);
            }
            if (kk < 63) {                      // own piece range
                vmax = fmaxf(vmax, v);
                const bool newp = spk && (kk > rel);
                const bool was0 = (ns == 0);
                const bool was1 = (ns == 1);
                const bool ge2  = (ns >= 2);
                fm = (newp && was1) ? cm : fm;
                const bool pm = newp && ge2;    // retire an interior piece
                msum += pm ? cm : 0.0f;
                mid0  = pm ? fmaxf(mid0, cm) : mid0;
                const float cm1 = fmaxf(cm, v);
                cm = newp ? v : (spk ? cm1 : cm);
                ns += newp ? 1 : 0;
                if (kk < 10)  tfk = (newp && was0) ? kk : tfk;
                if (kk >= 53) tlk = spk ? kk : tlk;
                rel = spk ? kk + 10 : rel;
            }
        }
    }
    const float lm = cm;
    if (ns == 1) fm = cm;

    // ---- publish chunk state ----
    s_ns[c][lane]   = ns;
    s_tf[c][lane]   = t0 + tfk;
    s_tl[c][lane]   = t0 + tlk;
    s_fm[c][lane]   = fm;
    s_lm[c][lane]   = lm;
    s_mid[c][lane]  = mid0;
    s_msum[c][lane] = msum;
    s_m0[c][lane]   = m0;
    s_vm[c][lane]   = vmax;
    __syncthreads();

    if (c == 0) {
        float m0g = NEGF, vmg = NEGF;
        #pragma unroll
        for (int cc = 0; cc < 8; ++cc) {
            m0g = fmaxf(m0g, s_m0[cc][lane]);
            vmg = fmaxf(vmg, s_vm[cc][lane]);
        }

        int nc = 0; float tot = 0.0f;
        float t40 = NEGF, t41 = NEGF, t42 = NEGF, t43 = NEGF;
        bool ov = false, valid = false;
        float open = NEGF; int last_t = -100000;
        #pragma unroll
        for (int cc = 0; cc < 8; ++cc) {
            const int nsc = s_ns[cc][lane];
            if (nsc == 0) continue;             // spike-free chunk
            const bool conn = (s_tf[cc][lane] - last_t) <= 10;
            if (conn) {
                open = fmaxf(open, s_fm[cc][lane]);
            } else {
                if (valid) { ++nc; tot += open; INS4(open); }
                open = s_fm[cc][lane]; valid = true;
            }
            if (nsc >= 2) {
                ++nc; tot += open; INS4(open);  // chain closes inside chunk
                const int mc = nsc - 2;         // interior pieces
                nc += mc; tot += s_msum[cc][lane];
                if (mc >= 1) INS4(s_mid[cc][lane]);
                if (mc >= 2) ov = true;         // top-4 may be inexact
                open = s_lm[cc][lane]; valid = true;
            }
            last_t = s_tl[cc][lane];
        }
        if (valid) { ++nc; tot += open; INS4(open); }

        float contrib = 0.0f;
        const int label = labels[neuron];
        if (label > nc) {
            const bool any_un = (m0g > -1.0e29f);
            if (!any_un) {
                contrib = vmg;                  // full0: everything masked
            } else {
                float m_rest;
                if (nc > 0) {
                    m_rest = m0g;     // argmax is a spike -> mask2 == mask
                } else {
                    int tm = 0; float vm = NEGF;   // cold: no spikes at all
                    for (int t = 0; t < 500; ++t) {
                        const float v = __ldg(p + t * 128);
                        if (v > vm) { vm = v; tm = t; }
                    }
                    float v2 = NEGF;
                    for (int t = 0; t < 500; ++t)
                        if (t < tm - 5 || t > tm + 5)
                            v2 = fmaxf(v2, __ldg(p + t * 128));
                    const bool full2 = (tm <= 5) && (tm + 5 >= 499);
                    m_rest = full2 ? vmg : v2;
                }
                const float dE = (float)(label - nc);
                contrib = -((m0g + (dE - 1.0f) * m_rest) / dE);
            }
        } else if (label < nc) {
            if (ov && label >= 1) {
                // rare exact top-4 recompute (serial rescan; t0 == 0 here)
                t40 = t41 = t42 = t43 = NEGF;
                int last = -1000; float cmx = NEGF; bool open2 = false;
                for (int t = 0; t < 500; ++t) {
                    const float v = __ldg(p + t * 128);
                    if (v >= 0.0f) {
                        if (t - last > 10) {
                            if (open2) INS4(cmx);
                            cmx = v; open2 = true;
                        } else cmx = fmaxf(cmx, v);
                        last = t;
                    }
                }
                if (open2) INS4(cmx);
            }
            float s = tot;                      // sum of (nc-label) smallest
            if (label >= 1) s -= t40;
            if (label >= 2) s -= t41;
            if (label >= 3) s -= t42;
            if (label >= 4) s -= t43;
            contrib = s / (float)(nc - label);
        }
        out[1 + neuron] = (float)nc;            // coalesced store

        float val = contrib;
        #pragma unroll
        for (int off = 16; off > 0; off >>= 1)
            val += __shfl_down_sync(0xffffffffu, val, off);
        if (lane == 0) atomicAdd(out, val);
    }
}

extern "C" void kernel_launch(void* const* d_in, const int* in_sizes, int n_in,
                              void* d_out, int out_size) {
    const float* vmem   = (const float*)d_in[0];
    const int*   labels = (const int*)d_in[2];
    float* out = (float*)d_out;

    atca_zero<<<1, 1>>>(out);
    // 32768 neurons / 32 per block = 1024 blocks of 256 (8 chunk-warps)
    atca8<<<1024, 256>>>(vmem, labels, out);
}